// round 11
// baseline (speedup 1.0000x reference)
#include <cuda_runtime.h>
#include <cstdint>

#define M_DIM 8192
#define N_DIM 8192
#define C_DIM 80

// R[c][n] = base[n] - pre_cls[n][c]   (2.6 MB; rows L1/L2-resident)
// out[m][:] = R[gt[m]][:]  (gather-broadcast copy).
__device__ float g_R[C_DIM * N_DIM];

// ---------------------------------------------------------------------------
// Kernel A: build R. 256 blocks x 32 n-rows x 512 threads. Coalesced float4
// loads into shared, softplus with 8 threads/row + shfl reduce, fast-math.
// Fires the PDL trigger at entry so the writer can launch + prefetch gt
// while we run.
// ---------------------------------------------------------------------------
#define TN    32
#define SPAD  88
#define ATHR  512

__global__ __launch_bounds__(ATHR)
void build_R_kernel(const float* __restrict__ pre)
{
    // Let the dependent (out_kernel) begin launching/pre-work immediately.
    cudaTriggerProgrammaticLaunchCompletion();

    __shared__ float S[TN * SPAD];
    __shared__ float base_sm[TN];

    const int tid = threadIdx.x;
    const int n0  = blockIdx.x * TN;

    // Coalesced load: 32 rows x 80 floats = 640 float4 (contiguous 10 KB).
    const float4* src = (const float4*)(pre + (size_t)n0 * C_DIM);
#pragma unroll
    for (int i = tid; i < TN * C_DIM / 4; i += ATHR) {
        float4 v = src[i];
        int l = 4 * i;
        *(float4*)&S[(l / C_DIM) * SPAD + (l % C_DIM)] = v;
    }
    __syncthreads();

    // Softplus: 8 threads per row, 10 c's each, subwarp shfl reduce.
    if (tid < 256) {
        const int r = tid >> 3;        // row 0..31
        const int q = tid & 7;         // subthread 0..7
        float s = 0.0f;
#pragma unroll
        for (int i = 0; i < 10; ++i) {
            float x = S[r * SPAD + q * 10 + i];
            s += fmaxf(x, 0.0f) + __logf(1.0f + __expf(-fabsf(x)));
        }
        s += __shfl_xor_sync(0xffffffffu, s, 4);
        s += __shfl_xor_sync(0xffffffffu, s, 2);
        s += __shfl_xor_sync(0xffffffffu, s, 1);
        if (q == 0) base_sm[r] = s;
    }
    __syncthreads();

    // R[c][n0+k] = base[k] - S[k][c]; 32-float coalesced runs per c.
#pragma unroll
    for (int j = tid; j < C_DIM * TN; j += ATHR) {
        int c = j >> 5;
        int k = j & 31;
        g_R[(size_t)c * N_DIM + n0 + k] = base_sm[k] - S[k * SPAD + c];
    }
}

// ---------------------------------------------------------------------------
// Kernel B: out[m][n] = R[gt[m]][n].  (PDL secondary)
// Pre-sync: fetch the 8 class indices (independent of g_R; uniform address
// per block -> warp broadcast, no smem, no barrier). Then grid-dependency
// sync, then the measured-optimal 8x (LDG.128 -> STG.128.cs) burst.
// ---------------------------------------------------------------------------
#define BTHREADS 256
#define MROWS    8
#define N4       (N_DIM / 4)     // 2048 float4 per row

__global__ __launch_bounds__(BTHREADS)
void out_kernel(const int* __restrict__ gt, float4* __restrict__ out)
{
    const int n4 = blockIdx.x * BTHREADS + threadIdx.x;
    const int m0 = blockIdx.y * MROWS;

    // Independent pre-work: class indices for our 8 rows (overlaps build_R).
    int g[MROWS];
#pragma unroll
    for (int r = 0; r < MROWS; ++r)
        g[r] = __ldg(&gt[m0 + r]);

    // Wait for build_R's g_R to be complete and visible.
    cudaGridDependencySynchronize();

    float4 v[MROWS];
#pragma unroll
    for (int r = 0; r < MROWS; ++r)
        v[r] = __ldg((const float4*)(g_R + (size_t)g[r] * N_DIM) + n4);

#pragma unroll
    for (int r = 0; r < MROWS; ++r)
        __stcs(&out[(size_t)(m0 + r) * N4 + n4], v[r]);
}

// ---------------------------------------------------------------------------
extern "C" void kernel_launch(void* const* d_in, const int* in_sizes, int n_in,
                              void* d_out, int out_size)
{
    const int*   gt  = (const int*)d_in[0];      // gt_kind_ind [M]
    const float* pre = (const float*)d_in[1];    // pre_cls [N, C]
    float4*      out = (float4*)d_out;           // [M, N] f32

    build_R_kernel<<<N_DIM / TN, ATHR>>>(pre);   // 256 blocks

    // Secondary with programmatic stream serialization (PDL).
    cudaLaunchConfig_t cfg = {};
    cfg.gridDim  = dim3(N4 / BTHREADS, M_DIM / MROWS);   // (8, 1024)
    cfg.blockDim = dim3(BTHREADS);
    cfg.dynamicSmemBytes = 0;
    cfg.stream = 0;
    cudaLaunchAttribute attr[1];
    attr[0].id = cudaLaunchAttributeProgrammaticStreamSerialization;
    attr[0].val.programmaticStreamSerializationAllowed = 1;
    cfg.attrs = attr;
    cfg.numAttrs = 1;
    cudaLaunchKernelEx(&cfg, out_kernel, gt, out);
}

// round 12
// speedup vs baseline: 1.4127x; 1.4127x over previous
#include <cuda_runtime.h>
#include <cstdint>

#define M_DIM 8192
#define N_DIM 8192
#define C_DIM 80

// R[c][n] = base[n] - pre_cls[n][c]   (2.6 MB; rows L1/L2-resident)
// out[m][:] = R[gt[m]][:]  (gather-broadcast copy).
__device__ float g_R[C_DIM * N_DIM];

// ---------------------------------------------------------------------------
// Kernel A: build R. 512 blocks x 16 n-rows x 256 threads (better SM coverage
// for this latency-bound prologue). Coalesced float4 loads into shared,
// softplus with 16 threads/row (5 c's each) + subwarp shfl reduce, fast-math.
// ---------------------------------------------------------------------------
#define TN   16
#define SPAD 88

__global__ __launch_bounds__(256)
void build_R_kernel(const float* __restrict__ pre)
{
    __shared__ float S[TN * SPAD];
    __shared__ float base_sm[TN];

    const int tid = threadIdx.x;
    const int n0  = blockIdx.x * TN;

    // Coalesced load: 16 rows x 80 floats = 320 float4 (contiguous 5 KB).
    const float4* src = (const float4*)(pre + (size_t)n0 * C_DIM);
#pragma unroll
    for (int i = tid; i < TN * C_DIM / 4; i += 256) {
        float4 v = src[i];
        int l = 4 * i;
        *(float4*)&S[(l / C_DIM) * SPAD + (l % C_DIM)] = v;
    }
    __syncthreads();

    // Softplus: 16 threads per row, 5 c's each, 16-lane shfl reduce.
    {
        const int r = tid >> 4;        // row 0..15
        const int q = tid & 15;        // subthread 0..15
        float s = 0.0f;
#pragma unroll
        for (int i = 0; i < 5; ++i) {
            float x = S[r * SPAD + q * 5 + i];
            s += fmaxf(x, 0.0f) + __logf(1.0f + __expf(-fabsf(x)));
        }
        s += __shfl_xor_sync(0xffffffffu, s, 8);
        s += __shfl_xor_sync(0xffffffffu, s, 4);
        s += __shfl_xor_sync(0xffffffffu, s, 2);
        s += __shfl_xor_sync(0xffffffffu, s, 1);
        if (q == 0) base_sm[r] = s;
    }
    __syncthreads();

    // R[c][n0+k] = base[k] - S[k][c]; 16-float coalesced runs per c.
#pragma unroll
    for (int j = tid; j < C_DIM * TN; j += 256) {
        int c = j >> 4;
        int k = j & 15;
        g_R[(size_t)c * N_DIM + n0 + k] = base_sm[k] - S[k * SPAD + c];
    }
}

// ---------------------------------------------------------------------------
// Kernel B: out[m][n] = R[gt[m]][n].  (R10 writer, grid TRANSPOSED)
// blockIdx.x = m-block, blockIdx.y = n-chunk: consecutive block-ids share the
// n-chunk, so each SM's co-resident blocks read the SAME 320 KB chip-wide
// working set (80 rows x 4 KB) -> max L1 reuse, minimal L2 read traffic.
// __ldg reads (L1-allocating), __stcs stores, 8 loads batched before stores.
// ---------------------------------------------------------------------------
#define BTHREADS 256
#define MROWS    8
#define N4       (N_DIM / 4)     // 2048 float4 per row

__global__ __launch_bounds__(BTHREADS)
void out_kernel(const int* __restrict__ gt, float4* __restrict__ out)
{
    const int n4 = blockIdx.y * BTHREADS + threadIdx.x;  // float4 index along n
    const int m0 = blockIdx.x * MROWS;

    __shared__ int sg[MROWS];
    if (threadIdx.x < MROWS) sg[threadIdx.x] = __ldg(&gt[m0 + threadIdx.x]);
    __syncthreads();

    float4 v[MROWS];
#pragma unroll
    for (int r = 0; r < MROWS; ++r)
        v[r] = __ldg((const float4*)(g_R + (size_t)sg[r] * N_DIM) + n4);

#pragma unroll
    for (int r = 0; r < MROWS; ++r)
        __stcs(&out[(size_t)(m0 + r) * N4 + n4], v[r]);
}

// ---------------------------------------------------------------------------
extern "C" void kernel_launch(void* const* d_in, const int* in_sizes, int n_in,
                              void* d_out, int out_size)
{
    const int*   gt  = (const int*)d_in[0];      // gt_kind_ind [M]
    const float* pre = (const float*)d_in[1];    // pre_cls [N, C]
    float4*      out = (float4*)d_out;           // [M, N] f32

    build_R_kernel<<<N_DIM / TN, 256>>>(pre);    // 512 blocks

    dim3 grid(M_DIM / MROWS, N4 / BTHREADS);     // (1024, 8) — transposed
    out_kernel<<<grid, BTHREADS>>>(gt, out);
}

// round 13
// speedup vs baseline: 1.5741x; 1.1142x over previous
#include <cuda_runtime.h>
#include <cstdint>

#define M_DIM 8192
#define N_DIM 8192
#define C_DIM 80

// R[c][n] = base[n] - pre_cls[n][c]   (2.6 MB; rows L1/L2-resident)
// out[m][:] = R[gt[m]][:]  (gather-broadcast copy).
__device__ float g_R[C_DIM * N_DIM];

// ---------------------------------------------------------------------------
// Kernel A: build R. 512 blocks x 16 n-rows x 256 threads (measured ~1.1 us
// exposed). Coalesced float4 loads into shared, softplus with 16 threads/row
// (5 c's each) + subwarp shfl reduce, fast-math (tol 1e-3, we sit ~6e-8).
// ---------------------------------------------------------------------------
#define TN   16
#define SPAD 88

__global__ __launch_bounds__(256)
void build_R_kernel(const float* __restrict__ pre)
{
    __shared__ float S[TN * SPAD];
    __shared__ float base_sm[TN];

    const int tid = threadIdx.x;
    const int n0  = blockIdx.x * TN;

    // Coalesced load: 16 rows x 80 floats = 320 float4 (contiguous 5 KB).
    const float4* src = (const float4*)(pre + (size_t)n0 * C_DIM);
#pragma unroll
    for (int i = tid; i < TN * C_DIM / 4; i += 256) {
        float4 v = src[i];
        int l = 4 * i;
        *(float4*)&S[(l / C_DIM) * SPAD + (l % C_DIM)] = v;
    }
    __syncthreads();

    // Softplus: 16 threads per row, 5 c's each, 16-lane shfl reduce.
    {
        const int r = tid >> 4;        // row 0..15
        const int q = tid & 15;        // subthread 0..15
        float s = 0.0f;
#pragma unroll
        for (int i = 0; i < 5; ++i) {
            float x = S[r * SPAD + q * 5 + i];
            s += fmaxf(x, 0.0f) + __logf(1.0f + __expf(-fabsf(x)));
        }
        s += __shfl_xor_sync(0xffffffffu, s, 8);
        s += __shfl_xor_sync(0xffffffffu, s, 4);
        s += __shfl_xor_sync(0xffffffffu, s, 2);
        s += __shfl_xor_sync(0xffffffffu, s, 1);
        if (q == 0) base_sm[r] = s;
    }
    __syncthreads();

    // R[c][n0+k] = base[k] - S[k][c]; 16-float coalesced runs per c.
#pragma unroll
    for (int j = tid; j < C_DIM * TN; j += 256) {
        int c = j >> 4;
        int k = j & 15;
        g_R[(size_t)c * N_DIM + n0 + k] = base_sm[k] - S[k * SPAD + c];
    }
}

// ---------------------------------------------------------------------------
// Kernel B: out[m][n] = R[gt[m]][n].  (R10 writer, verbatim — measured best)
// grid (8 n-chunks, 1024 m-groups): consecutive block-ids (x fastest) cover
// all 8 n-chunks of one m-group -> each scheduling neighborhood writes a
// 256 KB contiguous output region (DRAM write-page locality = the binding
// resource, per the R12 transpose experiment). __ldg reads (L1-allocating),
// __stcs streaming stores, all 8 loads batched before the store burst.
// ---------------------------------------------------------------------------
#define BTHREADS 256
#define MROWS    8
#define N4       (N_DIM / 4)     // 2048 float4 per row

__global__ __launch_bounds__(BTHREADS)
void out_kernel(const int* __restrict__ gt, float4* __restrict__ out)
{
    const int n4 = blockIdx.x * BTHREADS + threadIdx.x;
    const int m0 = blockIdx.y * MROWS;

    __shared__ int sg[MROWS];
    if (threadIdx.x < MROWS) sg[threadIdx.x] = __ldg(&gt[m0 + threadIdx.x]);
    __syncthreads();

    float4 v[MROWS];
#pragma unroll
    for (int r = 0; r < MROWS; ++r)
        v[r] = __ldg((const float4*)(g_R + (size_t)sg[r] * N_DIM) + n4);

#pragma unroll
    for (int r = 0; r < MROWS; ++r)
        __stcs(&out[(size_t)(m0 + r) * N4 + n4], v[r]);
}

// ---------------------------------------------------------------------------
extern "C" void kernel_launch(void* const* d_in, const int* in_sizes, int n_in,
                              void* d_out, int out_size)
{
    const int*   gt  = (const int*)d_in[0];      // gt_kind_ind [M]
    const float* pre = (const float*)d_in[1];    // pre_cls [N, C]
    float4*      out = (float4*)d_out;           // [M, N] f32

    build_R_kernel<<<N_DIM / TN, 256>>>(pre);    // 512 blocks, ~1.1 us exposed

    dim3 grid(N4 / BTHREADS, M_DIM / MROWS);     // (8, 1024)
    out_kernel<<<grid, BTHREADS>>>(gt, out);
}